// round 1
// baseline (speedup 1.0000x reference)
#include <cuda_runtime.h>
#include <math.h>

#define D       20
#define K1      30
#define NRELP1  201
#define NTIME   365
#define NLAYERS 3
#define MAXN    1000000

// ---------------- scratch (device globals; no allocation allowed) ----------------
__device__ __align__(16) float g_buf0[MAXN * D];            // 80 MB
__device__ __align__(16) float g_buf1[MAXN * D];            // 80 MB
__device__ __align__(16) float g_Pb[NRELP1 * K1];           // rela part of att MLP
__device__ __align__(16) float g_Pc[NRELP1 * K1];           // qrel part of att MLP
__device__ __align__(16) float g_RW[3 * NRELP1 * D];        // rela @ W_s^T
__device__ __align__(16) float g_TW[3 * NTIME * D];         // time @ W_s^T
__device__ __align__(16) float g_S0[NRELP1 * NRELP1];       // layer-0 sigmoid scores

// vectorized global float4 reduction (sm_90+)
__device__ __forceinline__ void red_add_v4(float* addr, float a, float b, float c, float d) {
    asm volatile(
        "{ .reg .u64 p; cvta.to.global.u64 p, %0;\n\t"
        "  red.global.add.v4.f32 [p], {%1, %2, %3, %4}; }\n\t"
        :: "l"(addr), "f"(a), "f"(b), "f"(c), "f"(d) : "memory");
}

__device__ __forceinline__ float leaky(float x) { return x > 0.f ? x : 0.01f * x; }

// ---------------- table precompute ----------------
__global__ void k_tables(const float* __restrict__ rela, const float* __restrict__ tem,
                         const float* __restrict__ w1,
                         const float* __restrict__ wp, const float* __restrict__ wn,
                         const float* __restrict__ wf)
{
    int i = blockIdx.x * blockDim.x + threadIdx.x;
    const int NPB = NRELP1 * K1;                 // 6030
    const int NRW = 3 * NRELP1 * D;              // 12060
    const int NTW = 3 * NTIME * D;               // 21900
    if (i < NPB) {                               // Pb[r][k] = rela[r] . w1[k][20:40]
        int r = i / K1, k = i % K1;
        float a = 0.f;
        #pragma unroll
        for (int j = 0; j < D; j++) a = fmaf(rela[r * D + j], w1[k * (3 * D) + D + j], a);
        g_Pb[i] = a;
    } else if (i < 2 * NPB) {                    // Pc[r][k] = rela[r] . w1[k][40:60]
        int t = i - NPB;
        int r = t / K1, k = t % K1;
        float a = 0.f;
        #pragma unroll
        for (int j = 0; j < D; j++) a = fmaf(rela[r * D + j], w1[k * (3 * D) + 2 * D + j], a);
        g_Pc[t] = a;
    } else if (i < 2 * NPB + NRW) {              // RW[s][r][o] = rela[r] . W_s[o]
        int t = i - 2 * NPB;
        int s = t / (NRELP1 * D);
        int rem = t % (NRELP1 * D);
        int r = rem / D, o = rem % D;
        const float* W = (s == 0) ? wp : ((s == 1) ? wn : wf);
        float a = 0.f;
        #pragma unroll
        for (int j = 0; j < D; j++) a = fmaf(rela[r * D + j], W[o * D + j], a);
        g_RW[t] = a;
    } else if (i < 2 * NPB + NRW + NTW) {        // TW[s][tt][o] = time[tt] . W_s[o]
        int t = i - 2 * NPB - NRW;
        int s = t / (NTIME * D);
        int rem = t % (NTIME * D);
        int tt = rem / D, o = rem % D;
        const float* W = (s == 0) ? wp : ((s == 1) ? wn : wf);
        float a = 0.f;
        #pragma unroll
        for (int j = 0; j < D; j++) a = fmaf(tem[tt * D + j], W[o * D + j], a);
        g_TW[t] = a;
    }
}

// layer-0 score table: h_src = 0 -> score depends only on (rel, qrel)
__global__ void k_s0(const float* __restrict__ w2)
{
    int i = blockIdx.x * blockDim.x + threadIdx.x;
    if (i >= NRELP1 * NRELP1) return;
    int r = i / NRELP1, q = i % NRELP1;
    float s = 0.f;
    #pragma unroll
    for (int k = 0; k < K1; k++) {
        float a = g_Pb[r * K1 + k] + g_Pc[q * K1 + k];
        a = fmaxf(a, 0.f);
        s = fmaf(a, w2[k], s);
    }
    g_S0[i] = 1.f / (1.f + __expf(-s));
}

// ---------------- layer 0: hidden == 0, pure gather/scale/scatter ----------------
__global__ __launch_bounds__(256) void k_edge0(
    const int* __restrict__ dst, const int* __restrict__ rel,
    const int* __restrict__ qrel, const int* __restrict__ rtime,
    float* __restrict__ hout, int E)
{
    int e = blockIdx.x * blockDim.x + threadIdx.x;
    if (e >= E) return;
    int dn = dst[e], r = rel[e], q = qrel[e], t = rtime[e];
    int sel = (t > 0) ? 2 : ((t == 0) ? 1 : 0);
    int ta = t < 0 ? -t : t;
    float score = g_S0[r * NRELP1 + q];
    const float4* rw = (const float4*)(g_RW + (sel * NRELP1 + r) * D);
    const float4* tw = (const float4*)(g_TW + (sel * NTIME + ta) * D);
    float* outp = hout + (size_t)dn * D;
    #pragma unroll
    for (int g = 0; g < D / 4; g++) {
        float4 a = rw[g];
        float4 b = tw[g];
        red_add_v4(outp + 4 * g,
                   score * (a.x + b.x), score * (a.y + b.y),
                   score * (a.z + b.z), score * (a.w + b.w));
    }
}

// ---------------- generic layer (layers 1..L-1) ----------------
__global__ __launch_bounds__(256) void k_edge(
    const int* __restrict__ src, const int* __restrict__ dst,
    const int* __restrict__ rel, const int* __restrict__ qrel,
    const int* __restrict__ rtime,
    const float* __restrict__ hin, float* __restrict__ hout,
    const float* __restrict__ w1, const float* __restrict__ w2,
    const float* __restrict__ wp, const float* __restrict__ wn,
    const float* __restrict__ wf, int E)
{
    __shared__ float sw1a[K1 * D];     // w_att1[:, 0:20] (h part)
    __shared__ float sw2[K1];
    __shared__ float sW[3 * D * D];    // past / now / future
    for (int i = threadIdx.x; i < K1 * D; i += blockDim.x)
        sw1a[i] = w1[(i / D) * (3 * D) + (i % D)];
    for (int i = threadIdx.x; i < K1; i += blockDim.x)
        sw2[i] = w2[i];
    for (int i = threadIdx.x; i < 3 * D * D; i += blockDim.x) {
        int s = i / (D * D); int rem = i % (D * D);
        sW[i] = ((s == 0) ? wp : ((s == 1) ? wn : wf))[rem];
    }
    __syncthreads();

    int e = blockIdx.x * blockDim.x + threadIdx.x;
    if (e >= E) return;
    int sn = src[e], dn = dst[e], r = rel[e], q = qrel[e], t = rtime[e];
    int sel = (t > 0) ? 2 : ((t == 0) ? 1 : 0);
    int ta = t < 0 ? -t : t;

    // gather + fused leaky_relu
    float h[D];
    const float4* hp = (const float4*)(hin + (size_t)sn * D);
    #pragma unroll
    for (int i = 0; i < D / 4; i++) {
        float4 v = hp[i];
        h[4 * i + 0] = leaky(v.x);
        h[4 * i + 1] = leaky(v.y);
        h[4 * i + 2] = leaky(v.z);
        h[4 * i + 3] = leaky(v.w);
    }

    // attention: a_k = h . w1a_k + Pb[rel][k] + Pc[qrel][k]
    const float* pb = g_Pb + r * K1;
    const float* pc = g_Pc + q * K1;
    float sacc = 0.f;
    for (int k = 0; k < K1; k++) {
        float a = pb[k] + pc[k];
        #pragma unroll
        for (int j = 0; j < D; j++) a = fmaf(h[j], sw1a[k * D + j], a);
        a = fmaxf(a, 0.f);
        sacc = fmaf(a, sw2[k], sacc);
    }
    float score = 1.f / (1.f + __expf(-sacc));

    // transformed = h @ W_sel^T + RW_row + TW_row ; msg = score * transformed
    const float* W  = sW + sel * D * D;
    const float* rw = g_RW + (sel * NRELP1 + r) * D;
    const float* tw = g_TW + (sel * NTIME + ta) * D;
    float* outp = hout + (size_t)dn * D;
    #pragma unroll
    for (int g = 0; g < D / 4; g++) {
        float mv[4];
        #pragma unroll
        for (int c = 0; c < 4; c++) {
            int i = 4 * g + c;
            float acc = rw[i] + tw[i];
            #pragma unroll
            for (int j = 0; j < D; j++) acc = fmaf(h[j], W[i * D + j], acc);
            mv[c] = score * acc;
        }
        red_add_v4(outp + 4 * g, mv[0], mv[1], mv[2], mv[3]);
    }
}

// ---------------- final: leaky -> dot(w_cls) + b -> scatter ----------------
__global__ __launch_bounds__(256) void k_final(
    const float* __restrict__ hin, const int* __restrict__ nb,
    const int* __restrict__ ne, const float* __restrict__ wcls,
    const float* __restrict__ bcls, const int* __restrict__ pne,
    float* __restrict__ out, int n)
{
    int i = blockIdx.x * blockDim.x + threadIdx.x;
    if (i >= n) return;
    const float4* hp = (const float4*)(hin + (size_t)i * D);
    float acc = bcls[0];
    #pragma unroll
    for (int g = 0; g < D / 4; g++) {
        float4 v = hp[g];
        acc = fmaf(leaky(v.x), __ldg(wcls + 4 * g + 0), acc);
        acc = fmaf(leaky(v.y), __ldg(wcls + 4 * g + 1), acc);
        acc = fmaf(leaky(v.z), __ldg(wcls + 4 * g + 2), acc);
        acc = fmaf(leaky(v.w), __ldg(wcls + 4 * g + 3), acc);
    }
    long long idx = (long long)nb[i] * (long long)pne[0] + (long long)ne[i];
    out[idx] = acc;
}

// ---------------- host ----------------
extern "C" void kernel_launch(void* const* d_in, const int* in_sizes, int n_in,
                              void* d_out, int out_size)
{
    const int*   src   = (const int*)d_in[0];
    const int*   dst   = (const int*)d_in[1];
    const int*   rel   = (const int*)d_in[2];
    const int*   qrel  = (const int*)d_in[3];
    const int*   rtime = (const int*)d_in[4];
    const int*   nb    = (const int*)d_in[5];
    const int*   ne    = (const int*)d_in[6];
    const float* rela  = (const float*)d_in[7];
    const float* tem   = (const float*)d_in[8];
    const float* w1    = (const float*)d_in[9];
    const float* w2    = (const float*)d_in[10];
    const float* wp    = (const float*)d_in[11];
    const float* wn    = (const float*)d_in[12];
    const float* wf    = (const float*)d_in[13];
    const float* wcls  = (const float*)d_in[14];
    const float* bcls  = (const float*)d_in[15];
    const int*   pne   = (const int*)d_in[17];

    int E  = in_sizes[0] / NLAYERS;
    int Nn = in_sizes[5];

    float *b0, *b1;
    cudaGetSymbolAddress((void**)&b0, g_buf0);
    cudaGetSymbolAddress((void**)&b1, g_buf1);
    size_t bufBytes = (size_t)Nn * D * sizeof(float);

    // precompute tables (independent of hidden state)
    const int NTAB = 2 * NRELP1 * K1 + 3 * NRELP1 * D + 3 * NTIME * D;
    k_tables<<<(NTAB + 255) / 256, 256>>>(rela, tem, w1, wp, wn, wf);
    k_s0<<<(NRELP1 * NRELP1 + 255) / 256, 256>>>(w2);

    int gE = (E + 255) / 256;

    // layer 0 (h = 0): accumulate into buf1
    cudaMemsetAsync(b1, 0, bufBytes);
    k_edge0<<<gE, 256>>>(dst, rel, qrel, rtime, b1, E);

    // layer 1: read act(buf1) -> accumulate buf0
    cudaMemsetAsync(b0, 0, bufBytes);
    k_edge<<<gE, 256>>>(src + E, dst + E, rel + E, qrel + E, rtime + E,
                        b1, b0, w1, w2, wp, wn, wf, E);

    // layer 2: read act(buf0) -> accumulate buf1
    cudaMemsetAsync(b1, 0, bufBytes);
    k_edge<<<gE, 256>>>(src + 2 * E, dst + 2 * E, rel + 2 * E, qrel + 2 * E, rtime + 2 * E,
                        b0, b1, w1, w2, wp, wn, wf, E);

    // output: zero then scatter
    cudaMemsetAsync(d_out, 0, (size_t)out_size * sizeof(float));
    k_final<<<(Nn + 255) / 256, 256>>>(b1, nb, ne, wcls, bcls, pne, (float*)d_out, Nn);
}